// round 5
// baseline (speedup 1.0000x reference)
#include <cuda_runtime.h>
#include <cuda_bf16.h>
#include <math.h>
#include <stdint.h>

// ---------------- problem constants ----------------
#define BATCH  2048
#define DDIM   32
#define CDIM   128
#define HID    512
#define INRAW  161
#define KP1    192
#define KP2    512
#define NSTEPS 16
#define NCTA   128

// ---------------- device scratch ----------------
__device__ __align__(16) __nv_bfloat16 g_x_hi [BATCH * KP1];
__device__ __align__(16) __nv_bfloat16 g_x_lo [BATCH * KP1];
__device__ __align__(16) __nv_bfloat16 g_h1_hi[BATCH * HID];
__device__ __align__(16) __nv_bfloat16 g_h1_lo[BATCH * HID];
__device__ __align__(16) __nv_bfloat16 g_h2_hi[BATCH * HID];
__device__ __align__(16) __nv_bfloat16 g_h2_lo[BATCH * HID];
__device__ __align__(16) float         g_theta[BATCH * DDIM];
__device__ __align__(16) float         g_ksum [BATCH * DDIM];
__device__ __align__(16) __nv_bfloat16 g_B1_hi[1024 * KP1];
__device__ __align__(16) __nv_bfloat16 g_B1_lo[1024 * KP1];
__device__ __align__(16) __nv_bfloat16 g_B2_hi[1024 * KP2];
__device__ __align__(16) __nv_bfloat16 g_B2_lo[1024 * KP2];
__device__ __align__(16) __nv_bfloat16 g_W3t_hi[DDIM * HID];
__device__ __align__(16) __nv_bfloat16 g_W3t_lo[DDIM * HID];
__device__ unsigned g_bar;

// ---------------- PTX helpers (compute_100-safe) ----------------
__device__ __forceinline__ uint32_t smem_u32(const void* p) {
    uint32_t a;
    asm("{ .reg .u64 t; cvta.to.shared.u64 t, %1; cvt.u32.u64 %0, t; }"
        : "=r"(a) : "l"(p));
    return a;
}
__device__ __forceinline__ void cpasync16(uint32_t saddr, const void* g) {
    asm volatile("cp.async.cg.shared.global [%0], [%1], 16;"
                 :: "r"(saddr), "l"(g) : "memory");
}
#define CP_COMMIT() asm volatile("cp.async.commit_group;" ::: "memory")
#define CP_WAIT0()  asm volatile("cp.async.wait_group 0;" ::: "memory")
#define CP_WAIT1()  asm volatile("cp.async.wait_group 1;" ::: "memory")

__device__ __forceinline__ void ldsm4(uint32_t* r, uint32_t addr) {
    asm volatile("ldmatrix.sync.aligned.m8n8.x4.shared.b16 {%0,%1,%2,%3}, [%4];"
                 : "=r"(r[0]), "=r"(r[1]), "=r"(r[2]), "=r"(r[3]) : "r"(addr));
}
__device__ __forceinline__ void mma16816(float* c, const uint32_t* a, const uint32_t* b) {
    asm volatile("mma.sync.aligned.m16n8k16.row.col.f32.bf16.bf16.f32 "
                 "{%0,%1,%2,%3}, {%4,%5,%6,%7}, {%8,%9}, {%0,%1,%2,%3};"
                 : "+f"(c[0]), "+f"(c[1]), "+f"(c[2]), "+f"(c[3])
                 : "r"(a[0]), "r"(a[1]), "r"(a[2]), "r"(a[3]),
                   "r"(b[0]), "r"(b[1]));
}
__device__ __forceinline__ void bf16split(float v, __nv_bfloat16& h, __nv_bfloat16& l) {
    h = __float2bfloat16(v);
    l = __float2bfloat16(v - __bfloat162float(h));
}

// ---------------- grid barrier (all 128 CTAs co-resident) ----------------
__device__ __forceinline__ void gsync(unsigned target) {
    __threadfence();
    __syncthreads();
    if (threadIdx.x == 0) {
        atomicAdd(&g_bar, 1u);
        volatile unsigned* p = &g_bar;
        while (*p < target) { __nanosleep(32); }
        __threadfence();
    }
    __syncthreads();
}

// ---------------- init kernels ----------------
__global__ void init_wt(const float* __restrict__ W, int Kraw, int Kpad,
                        __nv_bfloat16* __restrict__ dh, __nv_bfloat16* __restrict__ dl) {
    int idx = blockIdx.x * blockDim.x + threadIdx.x;
    if (idx >= 1024 * Kpad) return;
    int n = idx / Kpad, k = idx - n * Kpad;
    float v = (k < Kraw) ? W[(size_t)k * 1024 + n] : 0.0f;
    __nv_bfloat16 h, l; bf16split(v, h, l);
    dh[idx] = h; dl[idx] = l;
}

__global__ void init_w3t(const float* __restrict__ W3) {
    int idx = blockIdx.x * blockDim.x + threadIdx.x;
    if (idx == 0) g_bar = 0;                 // reset grid barrier each launch
    if (idx >= DDIM * HID) return;
    int n = idx >> 9, k = idx & 511;
    __nv_bfloat16 h, l; bf16split(W3[(size_t)k * DDIM + n], h, l);
    g_W3t_hi[idx] = h; g_W3t_lo[idx] = l;
}

__global__ void init_x(const float* __restrict__ theta0,
                       const float* __restrict__ context) {
    int r = blockIdx.x, t = threadIdx.x;
    float v;
    if (t < DDIM) {
        v = theta0[r * DDIM + t];
        g_theta[r * DDIM + t] = v;
    } else if (t == DDIM) {
        v = 0.0f;
    } else if (t < INRAW) {
        v = context[r * CDIM + (t - DDIM - 1)];
    } else {
        v = 0.0f;
    }
    __nv_bfloat16 h, l; bf16split(v, h, l);
    g_x_hi[(size_t)r * KP1 + t] = h;
    g_x_lo[(size_t)r * KP1 + t] = l;
}

// ---------------- GLU GEMM phase (device function) ----------------
#define ROWE  72
#define TILE_B (128 * ROWE * 2)
#define OFF_AH 0
#define OFF_AL (TILE_B)
#define OFF_BH (2 * TILE_B)
#define OFF_BL (3 * TILE_B)
#define STAGE_B (4 * TILE_B)            // 73728
#define PERS_SMEM (3 * STAGE_B)         // 221184

__device__ __forceinline__
void glu_phase(uint32_t sb,
               const __nv_bfloat16* __restrict__ Ah, const __nv_bfloat16* __restrict__ Al,
               int lda, int nch,
               const __nv_bfloat16* __restrict__ Bh, const __nv_bfloat16* __restrict__ Bl,
               int ldb, const float* __restrict__ bias,
               __nv_bfloat16* __restrict__ outh, __nv_bfloat16* __restrict__ outl,
               int bm, int bn) {
    const int tid  = threadIdx.x;
    const int lane = tid & 31, wid = tid >> 5;
    const int wm = wid & 3, wn = wid >> 2;

    float acc[2][8][4];
#pragma unroll
    for (int i = 0; i < 2; ++i)
#pragma unroll
        for (int j = 0; j < 8; ++j)
#pragma unroll
            for (int q = 0; q < 4; ++q) acc[i][j][q] = 0.0f;

    auto issue = [&](int c) {
        const int kc = c * 64;
        const uint32_t st = sb + (uint32_t)((c % 3) * STAGE_B);
#pragma unroll
        for (int p = 0; p < 4; ++p) {
            int slot = p * 256 + tid;
            int row = slot >> 3, cc = slot & 7;
            uint32_t so = (uint32_t)(row * ROWE + cc * 8) * 2;
            const __nv_bfloat16* gah = Ah + (size_t)(bm + row) * lda + kc + cc * 8;
            const __nv_bfloat16* gal = Al + (size_t)(bm + row) * lda + kc + cc * 8;
            int brow = (row < 64) ? (bn + row) : (448 + bn + row);
            const __nv_bfloat16* gbh = Bh + (size_t)brow * ldb + kc + cc * 8;
            const __nv_bfloat16* gbl = Bl + (size_t)brow * ldb + kc + cc * 8;
            cpasync16(st + OFF_AH + so, gah);
            cpasync16(st + OFF_AL + so, gal);
            cpasync16(st + OFF_BH + so, gbh);
            cpasync16(st + OFF_BL + so, gbl);
        }
        CP_COMMIT();
    };

    const uint32_t a_off = (uint32_t)((wm * 32 + (lane & 15)) * ROWE
                                      + ((lane >> 4) << 3)) * 2;
    const uint32_t b_off = (uint32_t)((wn * 32 + ((lane >> 4) << 3) + (lane & 7)) * ROWE
                                      + (((lane >> 3) & 1) << 3)) * 2;

    issue(0);
    if (nch > 1) issue(1);

    for (int c = 0; c < nch; ++c) {
        if (c + 1 < nch) CP_WAIT1(); else CP_WAIT0();
        __syncthreads();
        if (c + 2 < nch) issue(c + 2);

        const uint32_t st = sb + (uint32_t)((c % 3) * STAGE_B);
#pragma unroll
        for (int kk = 0; kk < 4; ++kk) {
            const uint32_t kb = (uint32_t)(kk * 16) * 2;
            uint32_t af[2][2][4];
#pragma unroll
            for (int mi = 0; mi < 2; ++mi) {
                uint32_t o = a_off + (uint32_t)(mi * 16 * ROWE) * 2 + kb;
                ldsm4(af[0][mi], st + OFF_AH + o);
                ldsm4(af[1][mi], st + OFF_AL + o);
            }
#pragma unroll
            for (int h = 0; h < 2; ++h) {
                uint32_t bfr[2][2][4];
#pragma unroll
                for (int p = 0; p < 2; ++p) {
                    uint32_t o = b_off + (uint32_t)((h * 64 + p * 16) * ROWE) * 2 + kb;
                    ldsm4(bfr[0][p], st + OFF_BH + o);
                    ldsm4(bfr[1][p], st + OFF_BL + o);
                }
#pragma unroll
                for (int mi = 0; mi < 2; ++mi)
#pragma unroll
                    for (int p = 0; p < 2; ++p)
#pragma unroll
                        for (int q = 0; q < 2; ++q) {
                            float* cc2 = acc[mi][h * 4 + p * 2 + q];
                            mma16816(cc2, af[0][mi], &bfr[0][p][q * 2]);
                            mma16816(cc2, af[0][mi], &bfr[1][p][q * 2]);
                            mma16816(cc2, af[1][mi], &bfr[0][p][q * 2]);
                        }
            }
        }
    }

    const int r0 = bm + wm * 32 + (lane >> 2);
    const int cb = wn * 32 + (lane & 3) * 2;
#pragma unroll
    for (int mi = 0; mi < 2; ++mi)
#pragma unroll
        for (int nt = 0; nt < 4; ++nt) {
            int gcol = bn + cb + nt * 8;
            float bia0 = bias[gcol],       bia1 = bias[gcol + 1];
            float bib0 = bias[512 + gcol], bib1 = bias[512 + gcol + 1];
            const float* ca = acc[mi][nt];
            const float* cbv = acc[mi][4 + nt];
            float g00 = (ca[0] + bia0) / (1.0f + __expf(-(cbv[0] + bib0)));
            float g01 = (ca[1] + bia1) / (1.0f + __expf(-(cbv[1] + bib1)));
            float g10 = (ca[2] + bia0) / (1.0f + __expf(-(cbv[2] + bib0)));
            float g11 = (ca[3] + bia1) / (1.0f + __expf(-(cbv[3] + bib1)));
            int ra = r0 + mi * 16;
            size_t o0 = (size_t)ra * HID + gcol;
            size_t o1 = (size_t)(ra + 8) * HID + gcol;
            __nv_bfloat16 h0, l0, h1, l1;
            bf16split(g00, h0, l0); bf16split(g01, h1, l1);
            *(__nv_bfloat162*)(outh + o0) = __nv_bfloat162(h0, h1);
            *(__nv_bfloat162*)(outl + o0) = __nv_bfloat162(l0, l1);
            bf16split(g10, h0, l0); bf16split(g11, h1, l1);
            *(__nv_bfloat162*)(outh + o1) = __nv_bfloat162(h0, h1);
            *(__nv_bfloat162*)(outl + o1) = __nv_bfloat162(l0, l1);
        }
}

// ---------------- layer-3 + RK4 phase (16 CTAs x 128 rows, 256 thr) ----------------
#define K3_WROW 520
#define K3_OFF_WH 0
#define K3_OFF_WL (32 * K3_WROW * 2)     // 33280
#define K3_AROW 72
#define K3_OFF_A (2 * 32 * K3_WROW * 2)  // 66560
#define K3_APREC (128 * K3_AROW * 2)     // 18432
#define K3_ASTG (2 * K3_APREC)           // 36864
// total: 66560 + 3*36864 = 177152 <= PERS_SMEM

__device__ __forceinline__
void k3_phase(uint32_t sb, const float* __restrict__ b3,
              int stage, float t_next, float dt, float* __restrict__ final_out,
              int bm) {
    const int tid = threadIdx.x, lane = tid & 31, w = tid >> 5;   // w: 0..7

    auto issueA = [&](int c) {
        const uint32_t st = sb + K3_OFF_A + (uint32_t)((c % 3) * K3_ASTG);
        const int kc = c * 64;
#pragma unroll
        for (int p = 0; p < 8; ++p) {
            int slot = p * 256 + tid;            // 0..2047
            int prec = slot >> 10;
            int s2 = slot & 1023;
            int row = s2 >> 3, cc = s2 & 7;
            uint32_t so = (uint32_t)(prec * K3_APREC + (row * K3_AROW + cc * 8) * 2);
            const __nv_bfloat16* g = (prec ? g_h2_lo : g_h2_hi)
                                     + (size_t)(bm + row) * HID + kc + cc * 8;
            cpasync16(st + so, g);
        }
        CP_COMMIT();
    };

    // W3t loads folded into group 0
#pragma unroll
    for (int p = 0; p < 16; ++p) {
        int slot = p * 256 + tid;                // 0..4095
        int prec = slot >> 11;
        int s2 = slot & 2047;
        int row = s2 >> 6, cc = s2 & 63;
        uint32_t so = (uint32_t)((prec ? K3_OFF_WL : K3_OFF_WH)
                                 + row * (K3_WROW * 2) + cc * 16);
        const __nv_bfloat16* g = (prec ? g_W3t_lo : g_W3t_hi) + (size_t)row * HID + cc * 8;
        cpasync16(sb + so, g);
    }
    issueA(0);
    issueA(1);

    float acc[4][4];
#pragma unroll
    for (int i = 0; i < 4; ++i)
#pragma unroll
        for (int j = 0; j < 4; ++j) acc[i][j] = 0.0f;

    const uint32_t a_base = (uint32_t)((w * 16 + (lane & 15)) * K3_AROW
                                       + ((lane >> 4) << 3)) * 2;

    for (int c = 0; c < 8; ++c) {
        if (c + 1 < 8) CP_WAIT1(); else CP_WAIT0();
        __syncthreads();
        if (c + 2 < 8) issueA(c + 2);

        const uint32_t st = sb + K3_OFF_A + (uint32_t)((c % 3) * K3_ASTG);
        const int kc = c * 64;
#pragma unroll
        for (int kk = 0; kk < 4; ++kk) {
            const uint32_t kb = (uint32_t)(kk * 16) * 2;
            uint32_t ah[4], al[4];
            ldsm4(ah, st + a_base + kb);
            ldsm4(al, st + K3_APREC + a_base + kb);
#pragma unroll
            for (int p = 0; p < 2; ++p) {
                uint32_t boff = (uint32_t)((p * 16 + ((lane >> 4) << 3) + (lane & 7)) * K3_WROW
                                           + kc + kk * 16 + (((lane >> 3) & 1) << 3)) * 2;
                uint32_t bh[4], bl[4];
                ldsm4(bh, sb + K3_OFF_WH + boff);
                ldsm4(bl, sb + K3_OFF_WL + boff);
#pragma unroll
                for (int q = 0; q < 2; ++q) {
                    float* cc2 = acc[p * 2 + q];
                    mma16816(cc2, ah, &bh[q * 2]);
                    mma16816(cc2, ah, &bl[q * 2]);
                    mma16816(cc2, al, &bh[q * 2]);
                }
            }
        }
    }

    const float dt6 = dt / 6.0f;
#pragma unroll
    for (int nt = 0; nt < 4; ++nt) {
        int col = (nt >> 1) * 16 + (nt & 1) * 8 + (lane & 3) * 2;
#pragma unroll
        for (int half = 0; half < 2; ++half) {
            int r = bm + w * 16 + (lane >> 2) + half * 8;
#pragma unroll
            for (int j = 0; j < 2; ++j) {
                int c = col + j;
                float kv = acc[nt][half * 2 + j] + b3[c];
                int ti = r * DDIM + c;
                float th = g_theta[ti];
                float arg;
                if (stage == 0)      { g_ksum[ti] = kv;         arg = th + 0.5f * dt * kv; }
                else if (stage == 1) { g_ksum[ti] += 2.0f * kv; arg = th + 0.5f * dt * kv; }
                else if (stage == 2) { g_ksum[ti] += 2.0f * kv; arg = th + dt * kv; }
                else {
                    float nth = th + dt6 * (g_ksum[ti] + kv);
                    g_theta[ti] = nth;
                    arg = nth;
                    if (final_out) final_out[ti] = nth;
                }
                __nv_bfloat16 h, l; bf16split(arg, h, l);
                g_x_hi[(size_t)r * KP1 + c] = h;
                g_x_lo[(size_t)r * KP1 + c] = l;
            }
        }
    }
    if ((lane & 3) == 0) {
        __nv_bfloat16 h, l; bf16split(t_next, h, l);
        int r = bm + w * 16 + (lane >> 2);
        g_x_hi[(size_t)r * KP1 + DDIM] = h;
        g_x_lo[(size_t)r * KP1 + DDIM] = l;
        g_x_hi[(size_t)(r + 8) * KP1 + DDIM] = h;
        g_x_lo[(size_t)(r + 8) * KP1 + DDIM] = l;
    }
}

// ---------------- persistent kernel ----------------
__global__ __launch_bounds__(256)
void persist(const float* __restrict__ b1, const float* __restrict__ b2,
             const float* __restrict__ b3, float* __restrict__ out) {
    extern __shared__ char smem[];
    const uint32_t sb = smem_u32(smem);
    const int cid = blockIdx.x;
    const int bm = (cid >> 3) * 128;
    const int bn = (cid & 7) * 64;
    const float dt = 1.0f / NSTEPS;

    unsigned ep = 0;
    for (int it = 0; it < NSTEPS * 4; ++it) {
        const int i = it >> 2, s = it & 3;
        const float t0 = (float)i * dt;
        const float t_next = (s <= 1) ? (t0 + 0.5f * dt) : (t0 + dt);

        glu_phase(sb, g_x_hi, g_x_lo, KP1, KP1 / 64, g_B1_hi, g_B1_lo, KP1,
                  b1, g_h1_hi, g_h1_lo, bm, bn);
        gsync(++ep * NCTA);

        glu_phase(sb, g_h1_hi, g_h1_lo, KP2, KP2 / 64, g_B2_hi, g_B2_lo, KP2,
                  b2, g_h2_hi, g_h2_lo, bm, bn);
        gsync(++ep * NCTA);

        if (cid < 16)
            k3_phase(sb, b3, s, t_next, dt,
                     (it == NSTEPS * 4 - 1) ? out : nullptr, cid * 128);
        gsync(++ep * NCTA);
    }
}

// ---------------- host launcher ----------------
extern "C" void kernel_launch(void* const* d_in, const int* in_sizes, int n_in,
                              void* d_out, int out_size) {
    const float* theta0  = (const float*)d_in[0];
    const float* context = (const float*)d_in[1];
    const float* W1      = (const float*)d_in[2];
    const float* b1      = (const float*)d_in[3];
    const float* W2      = (const float*)d_in[4];
    const float* b2      = (const float*)d_in[5];
    const float* W3      = (const float*)d_in[6];
    const float* b3      = (const float*)d_in[7];
    float* out = (float*)d_out;

    __nv_bfloat16 *b1h, *b1l, *b2h, *b2l;
    cudaGetSymbolAddress((void**)&b1h, g_B1_hi);
    cudaGetSymbolAddress((void**)&b1l, g_B1_lo);
    cudaGetSymbolAddress((void**)&b2h, g_B2_hi);
    cudaGetSymbolAddress((void**)&b2l, g_B2_lo);

    cudaFuncSetAttribute(persist, cudaFuncAttributeMaxDynamicSharedMemorySize, PERS_SMEM);

    init_wt<<<(1024 * KP1 + 255) / 256, 256>>>(W1, INRAW, KP1, b1h, b1l);
    init_wt<<<(1024 * KP2 + 255) / 256, 256>>>(W2, KP2,   KP2, b2h, b2l);
    init_w3t<<<(DDIM * HID + 255) / 256, 256>>>(W3);
    init_x<<<BATCH, KP1>>>(theta0, context);

    persist<<<NCTA, 256, PERS_SMEM>>>(b1, b2, b3, out);
}

// round 6
// speedup vs baseline: 1.3045x; 1.3045x over previous
#include <cuda_runtime.h>
#include <cuda_bf16.h>
#include <math.h>
#include <stdint.h>

// ---------------- problem constants ----------------
#define BATCH  2048
#define DDIM   32
#define CDIM   128
#define HID    512
#define INRAW  161
#define KP1    192
#define KP2    512
#define NSTEPS 16

// ---------------- device scratch ----------------
__device__ __align__(16) __nv_bfloat16 g_x_hi [BATCH * KP1];
__device__ __align__(16) __nv_bfloat16 g_x_lo [BATCH * KP1];
__device__ __align__(16) __nv_bfloat16 g_h1_hi[BATCH * HID];
__device__ __align__(16) __nv_bfloat16 g_h1_lo[BATCH * HID];
__device__ __align__(16) __nv_bfloat16 g_h2_hi[BATCH * HID];
__device__ __align__(16) __nv_bfloat16 g_h2_lo[BATCH * HID];
__device__ __align__(16) float         g_theta[BATCH * DDIM];
__device__ __align__(16) float         g_ksum [BATCH * DDIM];
__device__ __align__(16) __nv_bfloat16 g_B1_hi[1024 * KP1];
__device__ __align__(16) __nv_bfloat16 g_B1_lo[1024 * KP1];
__device__ __align__(16) __nv_bfloat16 g_B2_hi[1024 * KP2];
__device__ __align__(16) __nv_bfloat16 g_B2_lo[1024 * KP2];
__device__ __align__(16) __nv_bfloat16 g_W3t_hi[DDIM * HID];
__device__ __align__(16) __nv_bfloat16 g_W3t_lo[DDIM * HID];

// ---------------- PTX helpers (compute_100-safe) ----------------
__device__ __forceinline__ uint32_t smem_u32(const void* p) {
    uint32_t a;
    asm("{ .reg .u64 t; cvta.to.shared.u64 t, %1; cvt.u32.u64 %0, t; }"
        : "=r"(a) : "l"(p));
    return a;
}
__device__ __forceinline__ void cpasync16(uint32_t saddr, const void* g) {
    asm volatile("cp.async.cg.shared.global [%0], [%1], 16;"
                 :: "r"(saddr), "l"(g) : "memory");
}
#define CP_COMMIT() asm volatile("cp.async.commit_group;" ::: "memory")
#define CP_WAIT0()  asm volatile("cp.async.wait_group 0;" ::: "memory")
#define CP_WAIT1()  asm volatile("cp.async.wait_group 1;" ::: "memory")

__device__ __forceinline__ void ldsm4(uint32_t* r, uint32_t addr) {
    asm volatile("ldmatrix.sync.aligned.m8n8.x4.shared.b16 {%0,%1,%2,%3}, [%4];"
                 : "=r"(r[0]), "=r"(r[1]), "=r"(r[2]), "=r"(r[3]) : "r"(addr));
}
__device__ __forceinline__ void mma16816(float* c, const uint32_t* a, const uint32_t* b) {
    asm volatile("mma.sync.aligned.m16n8k16.row.col.f32.bf16.bf16.f32 "
                 "{%0,%1,%2,%3}, {%4,%5,%6,%7}, {%8,%9}, {%0,%1,%2,%3};"
                 : "+f"(c[0]), "+f"(c[1]), "+f"(c[2]), "+f"(c[3])
                 : "r"(a[0]), "r"(a[1]), "r"(a[2]), "r"(a[3]),
                   "r"(b[0]), "r"(b[1]));
}
__device__ __forceinline__ void bf16split(float v, __nv_bfloat16& h, __nv_bfloat16& l) {
    h = __float2bfloat16(v);
    l = __float2bfloat16(v - __bfloat162float(h));
}

// ---------------- init kernels ----------------
__global__ void init_wt(const float* __restrict__ W, int Kraw, int Kpad,
                        __nv_bfloat16* __restrict__ dh, __nv_bfloat16* __restrict__ dl) {
    int idx = blockIdx.x * blockDim.x + threadIdx.x;
    if (idx >= 1024 * Kpad) return;
    int n = idx / Kpad, k = idx - n * Kpad;
    float v = (k < Kraw) ? W[(size_t)k * 1024 + n] : 0.0f;
    __nv_bfloat16 h, l; bf16split(v, h, l);
    dh[idx] = h; dl[idx] = l;
}

__global__ void init_w3t(const float* __restrict__ W3) {
    int idx = blockIdx.x * blockDim.x + threadIdx.x;
    if (idx >= DDIM * HID) return;
    int n = idx >> 9, k = idx & 511;
    __nv_bfloat16 h, l; bf16split(W3[(size_t)k * DDIM + n], h, l);
    g_W3t_hi[idx] = h; g_W3t_lo[idx] = l;
}

__global__ void init_x(const float* __restrict__ theta0,
                       const float* __restrict__ context) {
    int r = blockIdx.x, t = threadIdx.x;
    float v;
    if (t < DDIM) {
        v = theta0[r * DDIM + t];
        g_theta[r * DDIM + t] = v;
    } else if (t == DDIM) {
        v = 0.0f;
    } else if (t < INRAW) {
        v = context[r * CDIM + (t - DDIM - 1)];
    } else {
        v = 0.0f;
    }
    __nv_bfloat16 h, l; bf16split(v, h, l);
    g_x_hi[(size_t)r * KP1 + t] = h;
    g_x_lo[(size_t)r * KP1 + t] = l;
}

// ---------------- fused bf16 mma.sync GEMM + GLU ----------------
// 512 threads, 16 warps in 4x4: warp = 32 rows x 16 cols (per GLU half).
// CTA: M=128, N=64 per half; BK=64; 3-stage cp.async pipeline.
#define ROWE  72
#define TILE_B (128 * ROWE * 2)
#define OFF_AH 0
#define OFF_AL (TILE_B)
#define OFF_BH (2 * TILE_B)
#define OFF_BL (3 * TILE_B)
#define STAGE_B (4 * TILE_B)            // 73728
#define GLU_SMEM (3 * STAGE_B)          // 221184

__global__ __launch_bounds__(512)
void glu_mma(const __nv_bfloat16* __restrict__ Ah, const __nv_bfloat16* __restrict__ Al,
             int lda, int nch,
             const __nv_bfloat16* __restrict__ Bh, const __nv_bfloat16* __restrict__ Bl,
             int ldb, const float* __restrict__ bias,
             __nv_bfloat16* __restrict__ outh, __nv_bfloat16* __restrict__ outl) {
    extern __shared__ char smem[];
    const uint32_t sb = smem_u32(smem);
    const int tid  = threadIdx.x;
    const int lane = tid & 31, wid = tid >> 5;
    const int wm = wid & 3;          // warp row: 32 rows
    const int wn = wid >> 2;         // warp col: 16 cols per half
    const int bm = blockIdx.y * 128, bn = blockIdx.x * 64;

    float acc[2][4][4];              // [mi][h*2+q][4]
#pragma unroll
    for (int i = 0; i < 2; ++i)
#pragma unroll
        for (int j = 0; j < 4; ++j)
#pragma unroll
            for (int q = 0; q < 4; ++q) acc[i][j][q] = 0.0f;

    auto issue = [&](int c) {
        const int kc = c * 64;
        const uint32_t st = sb + (uint32_t)((c % 3) * STAGE_B);
#pragma unroll
        for (int p = 0; p < 2; ++p) {
            int slot = p * 512 + tid;          // 0..1023
            int row = slot >> 3, cc = slot & 7;
            uint32_t so = (uint32_t)(row * ROWE + cc * 8) * 2;
            const __nv_bfloat16* gah = Ah + (size_t)(bm + row) * lda + kc + cc * 8;
            const __nv_bfloat16* gal = Al + (size_t)(bm + row) * lda + kc + cc * 8;
            int brow = (row < 64) ? (bn + row) : (448 + bn + row);
            const __nv_bfloat16* gbh = Bh + (size_t)brow * ldb + kc + cc * 8;
            const __nv_bfloat16* gbl = Bl + (size_t)brow * ldb + kc + cc * 8;
            cpasync16(st + OFF_AH + so, gah);
            cpasync16(st + OFF_AL + so, gal);
            cpasync16(st + OFF_BH + so, gbh);
            cpasync16(st + OFF_BL + so, gbl);
        }
        CP_COMMIT();
    };

    const uint32_t a_off = (uint32_t)((wm * 32 + (lane & 15)) * ROWE
                                      + ((lane >> 4) << 3)) * 2;
    const uint32_t b_off = (uint32_t)((wn * 16 + ((lane >> 4) << 3) + (lane & 7)) * ROWE
                                      + (((lane >> 3) & 1) << 3)) * 2;

    issue(0);
    if (nch > 1) issue(1);

    for (int c = 0; c < nch; ++c) {
        if (c + 1 < nch) CP_WAIT1(); else CP_WAIT0();
        __syncthreads();
        if (c + 2 < nch) issue(c + 2);

        const uint32_t st = sb + (uint32_t)((c % 3) * STAGE_B);
#pragma unroll
        for (int kk = 0; kk < 4; ++kk) {
            const uint32_t kb = (uint32_t)(kk * 16) * 2;
            uint32_t af[2][2][4];    // [prec][mi][4]
#pragma unroll
            for (int mi = 0; mi < 2; ++mi) {
                uint32_t o = a_off + (uint32_t)(mi * 16 * ROWE) * 2 + kb;
                ldsm4(af[0][mi], st + OFF_AH + o);
                ldsm4(af[1][mi], st + OFF_AL + o);
            }
#pragma unroll
            for (int h = 0; h < 2; ++h) {
                uint32_t bh4[4], bl4[4];
                uint32_t o = b_off + (uint32_t)(h * 64 * ROWE) * 2 + kb;
                ldsm4(bh4, st + OFF_BH + o);
                ldsm4(bl4, st + OFF_BL + o);
#pragma unroll
                for (int mi = 0; mi < 2; ++mi)
#pragma unroll
                    for (int q = 0; q < 2; ++q) {
                        float* cc2 = acc[mi][h * 2 + q];
                        mma16816(cc2, af[0][mi], &bh4[q * 2]);  // hi*hi
                        mma16816(cc2, af[0][mi], &bl4[q * 2]);  // hi*lo
                        mma16816(cc2, af[1][mi], &bh4[q * 2]);  // lo*hi
                    }
            }
        }
    }

    // ---------------- GLU epilogue (bf16 hi/lo out) ----------------
    const int r0 = bm + wm * 32 + (lane >> 2);
    const int cb = wn * 16 + (lane & 3) * 2;
#pragma unroll
    for (int mi = 0; mi < 2; ++mi)
#pragma unroll
        for (int q = 0; q < 2; ++q) {
            int gcol = bn + cb + q * 8;
            float bia0 = bias[gcol],       bia1 = bias[gcol + 1];
            float bib0 = bias[512 + gcol], bib1 = bias[512 + gcol + 1];
            const float* ca  = acc[mi][q];        // h=0 (a-half)
            const float* cbv = acc[mi][2 + q];    // h=1 (b-half)
            float g00 = (ca[0] + bia0) / (1.0f + __expf(-(cbv[0] + bib0)));
            float g01 = (ca[1] + bia1) / (1.0f + __expf(-(cbv[1] + bib1)));
            float g10 = (ca[2] + bia0) / (1.0f + __expf(-(cbv[2] + bib0)));
            float g11 = (ca[3] + bia1) / (1.0f + __expf(-(cbv[3] + bib1)));
            int ra = r0 + mi * 16;
            size_t o0 = (size_t)ra * HID + gcol;
            size_t o1 = (size_t)(ra + 8) * HID + gcol;
            __nv_bfloat16 h0, l0, h1, l1;
            bf16split(g00, h0, l0); bf16split(g01, h1, l1);
            *(__nv_bfloat162*)(outh + o0) = __nv_bfloat162(h0, h1);
            *(__nv_bfloat162*)(outl + o0) = __nv_bfloat162(l0, l1);
            bf16split(g10, h0, l0); bf16split(g11, h1, l1);
            *(__nv_bfloat162*)(outh + o1) = __nv_bfloat162(h0, h1);
            *(__nv_bfloat162*)(outl + o1) = __nv_bfloat162(l0, l1);
        }
}

// ---------------- layer 3 (mma) + fused RK4 stage update ----------------
#define K3_WROW 520
#define K3_OFF_WH 0
#define K3_OFF_WL (32 * K3_WROW * 2)     // 33280
#define K3_AROW 72
#define K3_OFF_A (2 * 32 * K3_WROW * 2)  // 66560
#define K3_APREC (64 * K3_AROW * 2)      // 9216
#define K3_ASTG (2 * K3_APREC)           // 18432
#define K3_SMEM (K3_OFF_A + 3 * K3_ASTG) // 121856

__global__ __launch_bounds__(128)
void k3_mma(const float* __restrict__ b3, int stage, float t_next, float dt,
            float* __restrict__ final_out) {
    extern __shared__ char smem[];
    const uint32_t sb = smem_u32(smem);
    const int tid = threadIdx.x, lane = tid & 31, w = tid >> 5;
    const int bm = blockIdx.x * 64;

    auto issueA = [&](int c) {
        const uint32_t st = sb + K3_OFF_A + (uint32_t)((c % 3) * K3_ASTG);
        const int kc = c * 64;
#pragma unroll
        for (int p = 0; p < 8; ++p) {
            int slot = p * 128 + tid;
            int prec = slot >> 9;
            int s2 = slot & 511;
            int row = s2 >> 3, cc = s2 & 7;
            uint32_t so = (uint32_t)(prec * K3_APREC + (row * K3_AROW + cc * 8) * 2);
            const __nv_bfloat16* g = (prec ? g_h2_lo : g_h2_hi)
                                     + (size_t)(bm + row) * HID + kc + cc * 8;
            cpasync16(st + so, g);
        }
        CP_COMMIT();
    };

#pragma unroll
    for (int p = 0; p < 32; ++p) {
        int slot = p * 128 + tid;
        int prec = slot >> 11;
        int s2 = slot & 2047;
        int row = s2 >> 6, cc = s2 & 63;
        uint32_t so = (uint32_t)((prec ? K3_OFF_WL : K3_OFF_WH)
                                 + row * (K3_WROW * 2) + cc * 16);
        const __nv_bfloat16* g = (prec ? g_W3t_lo : g_W3t_hi) + (size_t)row * HID + cc * 8;
        cpasync16(sb + so, g);
    }
    issueA(0);
    issueA(1);

    float acc[4][4];
#pragma unroll
    for (int i = 0; i < 4; ++i)
#pragma unroll
        for (int j = 0; j < 4; ++j) acc[i][j] = 0.0f;

    const uint32_t a_base = (uint32_t)((w * 16 + (lane & 15)) * K3_AROW
                                       + ((lane >> 4) << 3)) * 2;

    for (int c = 0; c < 8; ++c) {
        if (c + 1 < 8) CP_WAIT1(); else CP_WAIT0();
        __syncthreads();
        if (c + 2 < 8) issueA(c + 2);

        const uint32_t st = sb + K3_OFF_A + (uint32_t)((c % 3) * K3_ASTG);
        const int kc = c * 64;
#pragma unroll
        for (int kk = 0; kk < 4; ++kk) {
            const uint32_t kb = (uint32_t)(kk * 16) * 2;
            uint32_t ah[4], al[4];
            ldsm4(ah, st + a_base + kb);
            ldsm4(al, st + K3_APREC + a_base + kb);
#pragma unroll
            for (int p = 0; p < 2; ++p) {
                uint32_t boff = (uint32_t)((p * 16 + ((lane >> 4) << 3) + (lane & 7)) * K3_WROW
                                           + kc + kk * 16 + (((lane >> 3) & 1) << 3)) * 2;
                uint32_t bh[4], bl[4];
                ldsm4(bh, sb + K3_OFF_WH + boff);
                ldsm4(bl, sb + K3_OFF_WL + boff);
#pragma unroll
                for (int q = 0; q < 2; ++q) {
                    float* cc2 = acc[p * 2 + q];
                    mma16816(cc2, ah, &bh[q * 2]);
                    mma16816(cc2, ah, &bl[q * 2]);
                    mma16816(cc2, al, &bh[q * 2]);
                }
            }
        }
    }

    const float dt6 = dt / 6.0f;
#pragma unroll
    for (int nt = 0; nt < 4; ++nt) {
        int col = (nt >> 1) * 16 + (nt & 1) * 8 + (lane & 3) * 2;
#pragma unroll
        for (int half = 0; half < 2; ++half) {
            int r = bm + w * 16 + (lane >> 2) + half * 8;
#pragma unroll
            for (int j = 0; j < 2; ++j) {
                int c = col + j;
                float kv = acc[nt][half * 2 + j] + b3[c];
                int ti = r * DDIM + c;
                float th = g_theta[ti];
                float arg;
                if (stage == 0)      { g_ksum[ti] = kv;         arg = th + 0.5f * dt * kv; }
                else if (stage == 1) { g_ksum[ti] += 2.0f * kv; arg = th + 0.5f * dt * kv; }
                else if (stage == 2) { g_ksum[ti] += 2.0f * kv; arg = th + dt * kv; }
                else {
                    float nth = th + dt6 * (g_ksum[ti] + kv);
                    g_theta[ti] = nth;
                    arg = nth;
                    if (final_out) final_out[ti] = nth;
                }
                __nv_bfloat16 h, l; bf16split(arg, h, l);
                g_x_hi[(size_t)r * KP1 + c] = h;
                g_x_lo[(size_t)r * KP1 + c] = l;
            }
        }
    }
    if ((lane & 3) == 0) {
        __nv_bfloat16 h, l; bf16split(t_next, h, l);
        int r = bm + w * 16 + (lane >> 2);
        g_x_hi[(size_t)r * KP1 + DDIM] = h;
        g_x_lo[(size_t)r * KP1 + DDIM] = l;
        g_x_hi[(size_t)(r + 8) * KP1 + DDIM] = h;
        g_x_lo[(size_t)(r + 8) * KP1 + DDIM] = l;
    }
}

// ---------------- host launcher ----------------
extern "C" void kernel_launch(void* const* d_in, const int* in_sizes, int n_in,
                              void* d_out, int out_size) {
    const float* theta0  = (const float*)d_in[0];
    const float* context = (const float*)d_in[1];
    const float* W1      = (const float*)d_in[2];
    const float* b1      = (const float*)d_in[3];
    const float* W2      = (const float*)d_in[4];
    const float* b2      = (const float*)d_in[5];
    const float* W3      = (const float*)d_in[6];
    const float* b3      = (const float*)d_in[7];
    float* out = (float*)d_out;

    __nv_bfloat16 *xh, *xl, *h1h, *h1l, *h2h, *h2l, *b1h, *b1l, *b2h, *b2l;
    cudaGetSymbolAddress((void**)&xh,  g_x_hi);
    cudaGetSymbolAddress((void**)&xl,  g_x_lo);
    cudaGetSymbolAddress((void**)&h1h, g_h1_hi);
    cudaGetSymbolAddress((void**)&h1l, g_h1_lo);
    cudaGetSymbolAddress((void**)&h2h, g_h2_hi);
    cudaGetSymbolAddress((void**)&h2l, g_h2_lo);
    cudaGetSymbolAddress((void**)&b1h, g_B1_hi);
    cudaGetSymbolAddress((void**)&b1l, g_B1_lo);
    cudaGetSymbolAddress((void**)&b2h, g_B2_hi);
    cudaGetSymbolAddress((void**)&b2l, g_B2_lo);

    cudaFuncSetAttribute(glu_mma, cudaFuncAttributeMaxDynamicSharedMemorySize, GLU_SMEM);
    cudaFuncSetAttribute(k3_mma,  cudaFuncAttributeMaxDynamicSharedMemorySize, K3_SMEM);

    init_wt<<<(1024 * KP1 + 255) / 256, 256>>>(W1, INRAW, KP1, b1h, b1l);
    init_wt<<<(1024 * KP2 + 255) / 256, 256>>>(W2, KP2,   KP2, b2h, b2l);
    init_w3t<<<(DDIM * HID + 255) / 256, 256>>>(W3);
    init_x<<<BATCH, KP1>>>(theta0, context);

    const float dt = 1.0f / NSTEPS;
    dim3 ggrid(HID / 64, BATCH / 128);   // (8, 16)

    for (int i = 0; i < NSTEPS; ++i) {
        float t0 = (float)i * dt;
        for (int s = 0; s < 4; ++s) {
            glu_mma<<<ggrid, 512, GLU_SMEM>>>(xh, xl, KP1, KP1 / 64, b1h, b1l, KP1,
                                              b1, h1h, h1l);
            glu_mma<<<ggrid, 512, GLU_SMEM>>>(h1h, h1l, KP2, KP2 / 64, b2h, b2l, KP2,
                                              b2, h2h, h2l);
            float t_next = (s <= 1) ? (t0 + 0.5f * dt) : (t0 + dt);
            bool last = (i == NSTEPS - 1) && (s == 3);
            k3_mma<<<BATCH / 64, 128, K3_SMEM>>>(b3, s, t_next, dt,
                                                 last ? out : nullptr);
        }
    }
}

// round 7
// speedup vs baseline: 1.4983x; 1.1486x over previous
#include <cuda_runtime.h>
#include <cuda_bf16.h>
#include <math.h>
#include <stdint.h>

// ---------------- problem constants ----------------
#define BATCH  2048
#define DDIM   32
#define CDIM   128
#define HID    512
#define INRAW  161
#define KP1    192
#define KP2    512
#define NSTEPS 16

// ---------------- device scratch ----------------
__device__ __align__(16) __nv_bfloat16 g_x_hi [BATCH * KP1];
__device__ __align__(16) __nv_bfloat16 g_x_lo [BATCH * KP1];
__device__ __align__(16) __nv_bfloat16 g_h1_hi[BATCH * HID];
__device__ __align__(16) __nv_bfloat16 g_h1_lo[BATCH * HID];
__device__ __align__(16) float         g_theta[BATCH * DDIM];
__device__ __align__(16) float         g_ksum [BATCH * DDIM];
__device__ __align__(16) float         g_kpart[8 * BATCH * DDIM];   // per-bn partials
__device__ __align__(16) __nv_bfloat16 g_B1_hi[1024 * KP1];
__device__ __align__(16) __nv_bfloat16 g_B1_lo[1024 * KP1];
__device__ __align__(16) __nv_bfloat16 g_B2_hi[1024 * KP2];
__device__ __align__(16) __nv_bfloat16 g_B2_lo[1024 * KP2];
__device__ __align__(16) __nv_bfloat16 g_W3t_hi[DDIM * HID];
__device__ __align__(16) __nv_bfloat16 g_W3t_lo[DDIM * HID];

// ---------------- PTX helpers (compute_100-safe) ----------------
__device__ __forceinline__ uint32_t smem_u32(const void* p) {
    uint32_t a;
    asm("{ .reg .u64 t; cvta.to.shared.u64 t, %1; cvt.u32.u64 %0, t; }"
        : "=r"(a) : "l"(p));
    return a;
}
__device__ __forceinline__ void cpasync16(uint32_t saddr, const void* g) {
    asm volatile("cp.async.cg.shared.global [%0], [%1], 16;"
                 :: "r"(saddr), "l"(g) : "memory");
}
#define CP_COMMIT() asm volatile("cp.async.commit_group;" ::: "memory")
#define CP_WAIT0()  asm volatile("cp.async.wait_group 0;" ::: "memory")
#define CP_WAIT1()  asm volatile("cp.async.wait_group 1;" ::: "memory")

__device__ __forceinline__ void ldsm4(uint32_t* r, uint32_t addr) {
    asm volatile("ldmatrix.sync.aligned.m8n8.x4.shared.b16 {%0,%1,%2,%3}, [%4];"
                 : "=r"(r[0]), "=r"(r[1]), "=r"(r[2]), "=r"(r[3]) : "r"(addr));
}
__device__ __forceinline__ void mma16816(float* c, const uint32_t* a, const uint32_t* b) {
    asm volatile("mma.sync.aligned.m16n8k16.row.col.f32.bf16.bf16.f32 "
                 "{%0,%1,%2,%3}, {%4,%5,%6,%7}, {%8,%9}, {%0,%1,%2,%3};"
                 : "+f"(c[0]), "+f"(c[1]), "+f"(c[2]), "+f"(c[3])
                 : "r"(a[0]), "r"(a[1]), "r"(a[2]), "r"(a[3]),
                   "r"(b[0]), "r"(b[1]));
}
__device__ __forceinline__ void bf16split(float v, __nv_bfloat16& h, __nv_bfloat16& l) {
    h = __float2bfloat16(v);
    l = __float2bfloat16(v - __bfloat162float(h));
}

// ---------------- init kernels ----------------
__global__ void init_wt(const float* __restrict__ W, int Kraw, int Kpad,
                        __nv_bfloat16* __restrict__ dh, __nv_bfloat16* __restrict__ dl) {
    int idx = blockIdx.x * blockDim.x + threadIdx.x;
    if (idx >= 1024 * Kpad) return;
    int n = idx / Kpad, k = idx - n * Kpad;
    float v = (k < Kraw) ? W[(size_t)k * 1024 + n] : 0.0f;
    __nv_bfloat16 h, l; bf16split(v, h, l);
    dh[idx] = h; dl[idx] = l;
}

__global__ void init_w3t(const float* __restrict__ W3) {
    int idx = blockIdx.x * blockDim.x + threadIdx.x;
    if (idx >= DDIM * HID) return;
    int n = idx >> 9, k = idx & 511;
    __nv_bfloat16 h, l; bf16split(W3[(size_t)k * DDIM + n], h, l);
    g_W3t_hi[idx] = h; g_W3t_lo[idx] = l;
}

__global__ void init_x(const float* __restrict__ theta0,
                       const float* __restrict__ context) {
    int r = blockIdx.x, t = threadIdx.x;
    float v;
    if (t < DDIM) {
        v = theta0[r * DDIM + t];
        g_theta[r * DDIM + t] = v;
    } else if (t == DDIM) {
        v = 0.0f;
    } else if (t < INRAW) {
        v = context[r * CDIM + (t - DDIM - 1)];
    } else {
        v = 0.0f;
    }
    __nv_bfloat16 h, l; bf16split(v, h, l);
    g_x_hi[(size_t)r * KP1 + t] = h;
    g_x_lo[(size_t)r * KP1 + t] = l;
}

// ---------------- fused bf16 mma.sync GEMM + GLU (+ optional k3 partial) ----------------
// 512 threads, 16 warps in 4x4: warp = 32 rows x 16 cols (per GLU half).
// CTA: M=128, N=64 per half; BK=64; 3-stage cp.async pipeline.
// do_k3: instead of writing the GLU output, compute this CTA's partial of
// h2 @ W3 (128x32, K=64 slice) and store to g_kpart[bn][...].
#define ROWE  72
#define TILE_B (128 * ROWE * 2)
#define OFF_AH 0
#define OFF_AL (TILE_B)
#define OFF_BH (2 * TILE_B)
#define OFF_BL (3 * TILE_B)
#define STAGE_B (4 * TILE_B)            // 73728
#define W3_OFF  (3 * STAGE_B)           // 221184
#define W3_ROWB (72 * 2)                // row stride bytes (32 rows x 64+pad)
#define W3_PREC (32 * W3_ROWB)          // 4608
#define GLU_SMEM (W3_OFF + 2 * W3_PREC) // 230400
#define GLO  (128 * ROWE * 2)           // g-tile lo offset within stage0 (18432)

__global__ __launch_bounds__(512)
void glu_mma(const __nv_bfloat16* __restrict__ Ah, const __nv_bfloat16* __restrict__ Al,
             int lda, int nch,
             const __nv_bfloat16* __restrict__ Bh, const __nv_bfloat16* __restrict__ Bl,
             int ldb, const float* __restrict__ bias, int do_k3,
             __nv_bfloat16* __restrict__ outh, __nv_bfloat16* __restrict__ outl) {
    extern __shared__ char smem[];
    const uint32_t sb = smem_u32(smem);
    const int tid  = threadIdx.x;
    const int lane = tid & 31, wid = tid >> 5;
    const int wm = wid & 3;
    const int wn = wid >> 2;
    const int bm = blockIdx.y * 128, bn = blockIdx.x * 64;

    float acc[2][4][4];
#pragma unroll
    for (int i = 0; i < 2; ++i)
#pragma unroll
        for (int j = 0; j < 4; ++j)
#pragma unroll
            for (int q = 0; q < 4; ++q) acc[i][j][q] = 0.0f;

    auto issue = [&](int c) {
        const int kc = c * 64;
        const uint32_t st = sb + (uint32_t)((c % 3) * STAGE_B);
#pragma unroll
        for (int p = 0; p < 2; ++p) {
            int slot = p * 512 + tid;
            int row = slot >> 3, cc = slot & 7;
            uint32_t so = (uint32_t)(row * ROWE + cc * 8) * 2;
            const __nv_bfloat16* gah = Ah + (size_t)(bm + row) * lda + kc + cc * 8;
            const __nv_bfloat16* gal = Al + (size_t)(bm + row) * lda + kc + cc * 8;
            int brow = (row < 64) ? (bn + row) : (448 + bn + row);
            const __nv_bfloat16* gbh = Bh + (size_t)brow * ldb + kc + cc * 8;
            const __nv_bfloat16* gbl = Bl + (size_t)brow * ldb + kc + cc * 8;
            cpasync16(st + OFF_AH + so, gah);
            cpasync16(st + OFF_AL + so, gal);
            cpasync16(st + OFF_BH + so, gbh);
            cpasync16(st + OFF_BL + so, gbl);
        }
        if (c == 0 && do_k3) {
            // fold W3t slice load into chunk-0 group: 32 rows x 64 k, hi+lo
            int prec = tid >> 8;
            int s2 = tid & 255;
            int row = s2 >> 3, cc = s2 & 7;
            uint32_t so = (uint32_t)(W3_OFF + prec * W3_PREC + row * W3_ROWB + cc * 16);
            const __nv_bfloat16* g = (prec ? g_W3t_lo : g_W3t_hi)
                                     + (size_t)row * HID + bn + cc * 8;
            cpasync16(sb + so, g);
        }
        CP_COMMIT();
    };

    const uint32_t a_off = (uint32_t)((wm * 32 + (lane & 15)) * ROWE
                                      + ((lane >> 4) << 3)) * 2;
    const uint32_t b_off = (uint32_t)((wn * 16 + ((lane >> 4) << 3) + (lane & 7)) * ROWE
                                      + (((lane >> 3) & 1) << 3)) * 2;

    issue(0);
    if (nch > 1) issue(1);

    for (int c = 0; c < nch; ++c) {
        if (c + 1 < nch) CP_WAIT1(); else CP_WAIT0();
        __syncthreads();
        if (c + 2 < nch) issue(c + 2);

        const uint32_t st = sb + (uint32_t)((c % 3) * STAGE_B);
#pragma unroll
        for (int kk = 0; kk < 4; ++kk) {
            const uint32_t kb = (uint32_t)(kk * 16) * 2;
            uint32_t af[2][2][4];
#pragma unroll
            for (int mi = 0; mi < 2; ++mi) {
                uint32_t o = a_off + (uint32_t)(mi * 16 * ROWE) * 2 + kb;
                ldsm4(af[0][mi], st + OFF_AH + o);
                ldsm4(af[1][mi], st + OFF_AL + o);
            }
#pragma unroll
            for (int h = 0; h < 2; ++h) {
                uint32_t bh4[4], bl4[4];
                uint32_t o = b_off + (uint32_t)(h * 64 * ROWE) * 2 + kb;
                ldsm4(bh4, st + OFF_BH + o);
                ldsm4(bl4, st + OFF_BL + o);
#pragma unroll
                for (int mi = 0; mi < 2; ++mi)
#pragma unroll
                    for (int q = 0; q < 2; ++q) {
                        float* cc2 = acc[mi][h * 2 + q];
                        mma16816(cc2, af[0][mi], &bh4[q * 2]);
                        mma16816(cc2, af[0][mi], &bl4[q * 2]);
                        mma16816(cc2, af[1][mi], &bh4[q * 2]);
                    }
            }
        }
    }

    // ---------------- GLU epilogue ----------------
    const int r0 = bm + wm * 32 + (lane >> 2);
    const int cb = wn * 16 + (lane & 3) * 2;

    if (!do_k3) {
        // write GLU output hi/lo to global
#pragma unroll
        for (int mi = 0; mi < 2; ++mi)
#pragma unroll
            for (int q = 0; q < 2; ++q) {
                int gcol = bn + cb + q * 8;
                float bia0 = bias[gcol],       bia1 = bias[gcol + 1];
                float bib0 = bias[512 + gcol], bib1 = bias[512 + gcol + 1];
                const float* ca  = acc[mi][q];
                const float* cbv = acc[mi][2 + q];
                float g00 = (ca[0] + bia0) / (1.0f + __expf(-(cbv[0] + bib0)));
                float g01 = (ca[1] + bia1) / (1.0f + __expf(-(cbv[1] + bib1)));
                float g10 = (ca[2] + bia0) / (1.0f + __expf(-(cbv[2] + bib0)));
                float g11 = (ca[3] + bia1) / (1.0f + __expf(-(cbv[3] + bib1)));
                int ra = r0 + mi * 16;
                size_t o0 = (size_t)ra * HID + gcol;
                size_t o1 = (size_t)(ra + 8) * HID + gcol;
                __nv_bfloat16 h0, l0, h1, l1;
                bf16split(g00, h0, l0); bf16split(g01, h1, l1);
                *(__nv_bfloat162*)(outh + o0) = __nv_bfloat162(h0, h1);
                *(__nv_bfloat162*)(outl + o0) = __nv_bfloat162(l0, l1);
                bf16split(g10, h0, l0); bf16split(g11, h1, l1);
                *(__nv_bfloat162*)(outh + o1) = __nv_bfloat162(h0, h1);
                *(__nv_bfloat162*)(outl + o1) = __nv_bfloat162(l0, l1);
            }
        return;
    }

    // ---------------- fused k3 partial: kpart = g_tile(128x64) @ W3t_slice^T ----------------
    __syncthreads();   // mainloop smem reads done; reuse stage 0 for g tile
    {
        const uint32_t gs = sb;   // stage 0: hi at gs, lo at gs + GLO
#pragma unroll
        for (int mi = 0; mi < 2; ++mi)
#pragma unroll
            for (int q = 0; q < 2; ++q) {
                int gcol = bn + cb + q * 8;
                float bia0 = bias[gcol],       bia1 = bias[gcol + 1];
                float bib0 = bias[512 + gcol], bib1 = bias[512 + gcol + 1];
                const float* ca  = acc[mi][q];
                const float* cbv = acc[mi][2 + q];
                float g00 = (ca[0] + bia0) / (1.0f + __expf(-(cbv[0] + bib0)));
                float g01 = (ca[1] + bia1) / (1.0f + __expf(-(cbv[1] + bib1)));
                float g10 = (ca[2] + bia0) / (1.0f + __expf(-(cbv[2] + bib0)));
                float g11 = (ca[3] + bia1) / (1.0f + __expf(-(cbv[3] + bib1)));
                int lr = wm * 32 + (lane >> 2) + mi * 16;
                int lc = cb + q * 8;
                __nv_bfloat16 h0, l0, h1, l1;
                bf16split(g00, h0, l0); bf16split(g01, h1, l1);
                uint32_t o0 = (uint32_t)(lr * ROWE + lc) * 2;
                *(__nv_bfloat162*)(smem + o0)       = __nv_bfloat162(h0, h1);
                *(__nv_bfloat162*)(smem + GLO + o0) = __nv_bfloat162(l0, l1);
                bf16split(g10, h0, l0); bf16split(g11, h1, l1);
                uint32_t o1 = (uint32_t)((lr + 8) * ROWE + lc) * 2;
                *(__nv_bfloat162*)(smem + o1)       = __nv_bfloat162(h0, h1);
                *(__nv_bfloat162*)(smem + GLO + o1) = __nv_bfloat162(l0, l1);
            }
        __syncthreads();

        if (wid < 8) {
            float accs[4][4];
#pragma unroll
            for (int i = 0; i < 4; ++i)
#pragma unroll
                for (int j = 0; j < 4; ++j) accs[i][j] = 0.0f;

            const uint32_t a_b = gs + (uint32_t)((wid * 16 + (lane & 15)) * ROWE
                                                 + ((lane >> 4) << 3)) * 2;
            const uint32_t w_b = sb + W3_OFF
                + (uint32_t)(((lane >> 4) << 3) + (lane & 7)) * W3_ROWB
                + (uint32_t)((((lane >> 3) & 1) << 3)) * 2;
#pragma unroll
            for (int kk = 0; kk < 4; ++kk) {
                uint32_t ah[4], al[4];
                ldsm4(ah, a_b + kk * 32);
                ldsm4(al, a_b + GLO + kk * 32);
#pragma unroll
                for (int p = 0; p < 2; ++p) {
                    uint32_t bo = w_b + (uint32_t)(p * 16 * W3_ROWB) + kk * 32;
                    uint32_t bh4[4], bl4[4];
                    ldsm4(bh4, bo);
                    ldsm4(bl4, bo + W3_PREC);
#pragma unroll
                    for (int q = 0; q < 2; ++q) {
                        float* cc2 = accs[p * 2 + q];
                        mma16816(cc2, ah, &bh4[q * 2]);
                        mma16816(cc2, ah, &bl4[q * 2]);
                        mma16816(cc2, al, &bh4[q * 2]);
                    }
                }
            }
            // write partials: kpart[bnIdx][bm+row][col]
            float* kp = g_kpart + (size_t)blockIdx.x * (BATCH * DDIM);
#pragma unroll
            for (int nt = 0; nt < 4; ++nt)
#pragma unroll
                for (int half = 0; half < 2; ++half) {
                    int lr = wid * 16 + (lane >> 2) + half * 8;
                    int col = nt * 8 + (lane & 3) * 2;
                    *(float2*)(kp + (size_t)(bm + lr) * DDIM + col)
                        = make_float2(accs[nt][half * 2], accs[nt][half * 2 + 1]);
                }
        }
    }
}

// ---------------- RK4 stage update (elementwise) ----------------
__global__ __launch_bounds__(256)
void update(const float* __restrict__ b3, int stage, float t_next, float dt,
            float* __restrict__ final_out) {
    int idx = blockIdx.x * 256 + threadIdx.x;    // 0..65535
    int r = idx >> 5, c = idx & 31;
    float kv = b3[c];
#pragma unroll
    for (int b = 0; b < 8; ++b)
        kv += g_kpart[(size_t)b * (BATCH * DDIM) + idx];

    float th = g_theta[idx];
    float arg;
    if (stage == 0)      { g_ksum[idx] = kv;         arg = th + 0.5f * dt * kv; }
    else if (stage == 1) { g_ksum[idx] += 2.0f * kv; arg = th + 0.5f * dt * kv; }
    else if (stage == 2) { g_ksum[idx] += 2.0f * kv; arg = th + dt * kv; }
    else {
        float nth = th + (dt / 6.0f) * (g_ksum[idx] + kv);
        g_theta[idx] = nth;
        arg = nth;
        if (final_out) final_out[idx] = nth;
    }
    __nv_bfloat16 h, l; bf16split(arg, h, l);
    g_x_hi[(size_t)r * KP1 + c] = h;
    g_x_lo[(size_t)r * KP1 + c] = l;
    if (c == 0) {
        __nv_bfloat16 th2, tl2; bf16split(t_next, th2, tl2);
        g_x_hi[(size_t)r * KP1 + DDIM] = th2;
        g_x_lo[(size_t)r * KP1 + DDIM] = tl2;
    }
}

// ---------------- host launcher ----------------
extern "C" void kernel_launch(void* const* d_in, const int* in_sizes, int n_in,
                              void* d_out, int out_size) {
    const float* theta0  = (const float*)d_in[0];
    const float* context = (const float*)d_in[1];
    const float* W1      = (const float*)d_in[2];
    const float* b1      = (const float*)d_in[3];
    const float* W2      = (const float*)d_in[4];
    const float* b2      = (const float*)d_in[5];
    const float* W3      = (const float*)d_in[6];
    const float* b3      = (const float*)d_in[7];
    float* out = (float*)d_out;

    __nv_bfloat16 *xh, *xl, *h1h, *h1l, *b1h, *b1l, *b2h, *b2l;
    cudaGetSymbolAddress((void**)&xh,  g_x_hi);
    cudaGetSymbolAddress((void**)&xl,  g_x_lo);
    cudaGetSymbolAddress((void**)&h1h, g_h1_hi);
    cudaGetSymbolAddress((void**)&h1l, g_h1_lo);
    cudaGetSymbolAddress((void**)&b1h, g_B1_hi);
    cudaGetSymbolAddress((void**)&b1l, g_B1_lo);
    cudaGetSymbolAddress((void**)&b2h, g_B2_hi);
    cudaGetSymbolAddress((void**)&b2l, g_B2_lo);

    cudaFuncSetAttribute(glu_mma, cudaFuncAttributeMaxDynamicSharedMemorySize, GLU_SMEM);

    init_wt<<<(1024 * KP1 + 255) / 256, 256>>>(W1, INRAW, KP1, b1h, b1l);
    init_wt<<<(1024 * KP2 + 255) / 256, 256>>>(W2, KP2,   KP2, b2h, b2l);
    init_w3t<<<(DDIM * HID + 255) / 256, 256>>>(W3);
    init_x<<<BATCH, KP1>>>(theta0, context);

    const float dt = 1.0f / NSTEPS;
    dim3 ggrid(HID / 64, BATCH / 128);   // (8, 16)

    for (int i = 0; i < NSTEPS; ++i) {
        float t0 = (float)i * dt;
        for (int s = 0; s < 4; ++s) {
            glu_mma<<<ggrid, 512, GLU_SMEM>>>(xh, xl, KP1, KP1 / 64, b1h, b1l, KP1,
                                              b1, 0, h1h, h1l);
            glu_mma<<<ggrid, 512, GLU_SMEM>>>(h1h, h1l, KP2, KP2 / 64, b2h, b2l, KP2,
                                              b2, 1, nullptr, nullptr);
            float t_next = (s <= 1) ? (t0 + 0.5f * dt) : (t0 + dt);
            bool last = (i == NSTEPS - 1) && (s == 3);
            update<<<BATCH * DDIM / 256, 256>>>(b3, s, t_next, dt,
                                                last ? out : nullptr);
        }
    }
}

// round 8
// speedup vs baseline: 1.7188x; 1.1471x over previous
#include <cuda_runtime.h>
#include <cuda_bf16.h>
#include <math.h>
#include <stdint.h>

// ---------------- problem constants ----------------
#define BATCH  2048
#define DDIM   32
#define CDIM   128
#define HID    512
#define NSTEPS 16
#define NELEM  (BATCH * DDIM)

// ---------------- device scratch ----------------
__device__ __align__(16) __nv_bfloat16 g_h1_hi[BATCH * HID];
__device__ __align__(16) __nv_bfloat16 g_h1_lo[BATCH * HID];
__device__ __align__(16) float         g_theta2[2][NELEM];
__device__ __align__(16) float         g_ksum2 [2][NELEM];
__device__ __align__(16) float         g_kpart[8 * NELEM];
__device__ __align__(16) __nv_bfloat16 g_B1t_hi[1024 * 32];    // W1 theta rows, transposed
__device__ __align__(16) __nv_bfloat16 g_B1t_lo[1024 * 32];
__device__ __align__(16) __nv_bfloat16 g_B1c_hi[1024 * 128];   // W1 ctx rows, transposed
__device__ __align__(16) __nv_bfloat16 g_B1c_lo[1024 * 128];
__device__ __align__(16) __nv_bfloat16 g_B2_hi[1024 * HID];
__device__ __align__(16) __nv_bfloat16 g_B2_lo[1024 * HID];
__device__ __align__(16) __nv_bfloat16 g_W3t_hi[DDIM * HID];
__device__ __align__(16) __nv_bfloat16 g_W3t_lo[DDIM * HID];
__device__ __align__(16) __nv_bfloat16 g_ctx_hi[BATCH * 128];
__device__ __align__(16) __nv_bfloat16 g_ctx_lo[BATCH * 128];
__device__ __align__(16) float         g_C0[BATCH * 1024];     // ctx@W1c + b1

// ---------------- PTX helpers (compute_100-safe) ----------------
__device__ __forceinline__ uint32_t smem_u32(const void* p) {
    uint32_t a;
    asm("{ .reg .u64 t; cvta.to.shared.u64 t, %1; cvt.u32.u64 %0, t; }"
        : "=r"(a) : "l"(p));
    return a;
}
__device__ __forceinline__ void cpasync16(uint32_t saddr, const void* g) {
    asm volatile("cp.async.cg.shared.global [%0], [%1], 16;"
                 :: "r"(saddr), "l"(g) : "memory");
}
#define CP_COMMIT() asm volatile("cp.async.commit_group;" ::: "memory")
#define CP_WAIT0()  asm volatile("cp.async.wait_group 0;" ::: "memory")
#define CP_WAIT1()  asm volatile("cp.async.wait_group 1;" ::: "memory")

__device__ __forceinline__ void ldsm4(uint32_t* r, uint32_t addr) {
    asm volatile("ldmatrix.sync.aligned.m8n8.x4.shared.b16 {%0,%1,%2,%3}, [%4];"
                 : "=r"(r[0]), "=r"(r[1]), "=r"(r[2]), "=r"(r[3]) : "r"(addr));
}
__device__ __forceinline__ void mma16816(float* c, const uint32_t* a, const uint32_t* b) {
    asm volatile("mma.sync.aligned.m16n8k16.row.col.f32.bf16.bf16.f32 "
                 "{%0,%1,%2,%3}, {%4,%5,%6,%7}, {%8,%9}, {%0,%1,%2,%3};"
                 : "+f"(c[0]), "+f"(c[1]), "+f"(c[2]), "+f"(c[3])
                 : "r"(a[0]), "r"(a[1]), "r"(a[2]), "r"(a[3]),
                   "r"(b[0]), "r"(b[1]));
}
__device__ __forceinline__ void bf16split(float v, __nv_bfloat16& h, __nv_bfloat16& l) {
    h = __float2bfloat16(v);
    l = __float2bfloat16(v - __bfloat162float(h));
}

// ---------------- init kernels ----------------
__global__ void init_b1t(const float* __restrict__ W1) {
    int idx = blockIdx.x * 256 + threadIdx.x;          // 1024*32
    int n = idx >> 5, k = idx & 31;
    __nv_bfloat16 h, l; bf16split(W1[(size_t)k * 1024 + n], h, l);
    g_B1t_hi[idx] = h; g_B1t_lo[idx] = l;
}
__global__ void init_b1c(const float* __restrict__ W1) {
    int idx = blockIdx.x * 256 + threadIdx.x;          // 1024*128
    int n = idx >> 7, k = idx & 127;
    __nv_bfloat16 h, l; bf16split(W1[(size_t)(33 + k) * 1024 + n], h, l);
    g_B1c_hi[idx] = h; g_B1c_lo[idx] = l;
}
__global__ void init_b2(const float* __restrict__ W2) {
    int idx = blockIdx.x * 256 + threadIdx.x;          // 1024*512
    int n = idx >> 9, k = idx & 511;
    __nv_bfloat16 h, l; bf16split(W2[(size_t)k * 1024 + n], h, l);
    g_B2_hi[idx] = h; g_B2_lo[idx] = l;
}
__global__ void init_w3t(const float* __restrict__ W3) {
    int idx = blockIdx.x * 256 + threadIdx.x;          // 32*512
    int n = idx >> 9, k = idx & 511;
    __nv_bfloat16 h, l; bf16split(W3[(size_t)k * DDIM + n], h, l);
    g_W3t_hi[idx] = h; g_W3t_lo[idx] = l;
}
__global__ void init_ctx(const float* __restrict__ context) {
    int idx = blockIdx.x * 256 + threadIdx.x;          // 2048*128
    __nv_bfloat16 h, l; bf16split(context[idx], h, l);
    g_ctx_hi[idx] = h; g_ctx_lo[idx] = l;
}
__global__ void init_theta(const float* __restrict__ theta0) {
    int idx = blockIdx.x * 256 + threadIdx.x;          // 65536
    g_theta2[0][idx] = theta0[idx];
}

// ---------------- big GEMM kernel (layer2 GLU+k3, or C0 build) ----------------
// 512 threads, 16 warps 4x4; CTA: M=128, N=64 per half; BK=64; 3-stage pipeline.
// mode 0: out = A@B + bias (fp32, to outf [2048x1024])   -- C0 build
// mode 1: g = GLU(A@B+bias); kpart[bn] = g @ W3t_slice^T -- layer2 fused k3
#define ROWE  72
#define TILE_B (128 * ROWE * 2)
#define OFF_AH 0
#define OFF_AL (TILE_B)
#define OFF_BH (2 * TILE_B)
#define OFF_BL (3 * TILE_B)
#define STAGE_B (4 * TILE_B)            // 73728
#define W3_OFF  (3 * STAGE_B)           // 221184
#define W3_ROWB (72 * 2)
#define W3_PREC (32 * W3_ROWB)          // 4608
#define GLU_SMEM (W3_OFF + 2 * W3_PREC) // 230400
#define GLO  (128 * ROWE * 2)

__global__ __launch_bounds__(512)
void glu_mma(const __nv_bfloat16* __restrict__ Ah, const __nv_bfloat16* __restrict__ Al,
             int lda, int nch,
             const __nv_bfloat16* __restrict__ Bh, const __nv_bfloat16* __restrict__ Bl,
             int ldb, const float* __restrict__ bias, int mode,
             float* __restrict__ outf) {
    extern __shared__ char smem[];
    const uint32_t sb = smem_u32(smem);
    const int tid  = threadIdx.x;
    const int lane = tid & 31, wid = tid >> 5;
    const int wm = wid & 3;
    const int wn = wid >> 2;
    const int bm = blockIdx.y * 128, bn = blockIdx.x * 64;

    float acc[2][4][4];
#pragma unroll
    for (int i = 0; i < 2; ++i)
#pragma unroll
        for (int j = 0; j < 4; ++j)
#pragma unroll
            for (int q = 0; q < 4; ++q) acc[i][j][q] = 0.0f;

    auto issue = [&](int c) {
        const int kc = c * 64;
        const uint32_t st = sb + (uint32_t)((c % 3) * STAGE_B);
#pragma unroll
        for (int p = 0; p < 2; ++p) {
            int slot = p * 512 + tid;
            int row = slot >> 3, cc = slot & 7;
            uint32_t so = (uint32_t)(row * ROWE + cc * 8) * 2;
            const __nv_bfloat16* gah = Ah + (size_t)(bm + row) * lda + kc + cc * 8;
            const __nv_bfloat16* gal = Al + (size_t)(bm + row) * lda + kc + cc * 8;
            int brow = (row < 64) ? (bn + row) : (448 + bn + row);
            const __nv_bfloat16* gbh = Bh + (size_t)brow * ldb + kc + cc * 8;
            const __nv_bfloat16* gbl = Bl + (size_t)brow * ldb + kc + cc * 8;
            cpasync16(st + OFF_AH + so, gah);
            cpasync16(st + OFF_AL + so, gal);
            cpasync16(st + OFF_BH + so, gbh);
            cpasync16(st + OFF_BL + so, gbl);
        }
        if (c == 0 && mode == 1) {
            int prec = tid >> 8;
            int s2 = tid & 255;
            int row = s2 >> 3, cc = s2 & 7;
            uint32_t so = (uint32_t)(W3_OFF + prec * W3_PREC + row * W3_ROWB + cc * 16);
            const __nv_bfloat16* g = (prec ? g_W3t_lo : g_W3t_hi)
                                     + (size_t)row * HID + bn + cc * 8;
            cpasync16(sb + so, g);
        }
        CP_COMMIT();
    };

    const uint32_t a_off = (uint32_t)((wm * 32 + (lane & 15)) * ROWE
                                      + ((lane >> 4) << 3)) * 2;
    const uint32_t b_off = (uint32_t)((wn * 16 + ((lane >> 4) << 3) + (lane & 7)) * ROWE
                                      + (((lane >> 3) & 1) << 3)) * 2;

    issue(0);
    if (nch > 1) issue(1);

    for (int c = 0; c < nch; ++c) {
        if (c + 1 < nch) CP_WAIT1(); else CP_WAIT0();
        __syncthreads();
        if (c + 2 < nch) issue(c + 2);

        const uint32_t st = sb + (uint32_t)((c % 3) * STAGE_B);
#pragma unroll
        for (int kk = 0; kk < 4; ++kk) {
            const uint32_t kb = (uint32_t)(kk * 16) * 2;
            uint32_t af[2][2][4];
#pragma unroll
            for (int mi = 0; mi < 2; ++mi) {
                uint32_t o = a_off + (uint32_t)(mi * 16 * ROWE) * 2 + kb;
                ldsm4(af[0][mi], st + OFF_AH + o);
                ldsm4(af[1][mi], st + OFF_AL + o);
            }
#pragma unroll
            for (int h = 0; h < 2; ++h) {
                uint32_t bh4[4], bl4[4];
                uint32_t o = b_off + (uint32_t)(h * 64 * ROWE) * 2 + kb;
                ldsm4(bh4, st + OFF_BH + o);
                ldsm4(bl4, st + OFF_BL + o);
#pragma unroll
                for (int mi = 0; mi < 2; ++mi)
#pragma unroll
                    for (int q = 0; q < 2; ++q) {
                        float* cc2 = acc[mi][h * 2 + q];
                        mma16816(cc2, af[0][mi], &bh4[q * 2]);
                        mma16816(cc2, af[0][mi], &bl4[q * 2]);
                        mma16816(cc2, af[1][mi], &bh4[q * 2]);
                    }
            }
        }
    }

    const int r0 = bm + wm * 32 + (lane >> 2);
    const int cb = wn * 16 + (lane & 3) * 2;

    if (mode == 0) {
        // C0 build: write acc + bias (fp32) to outf[2048][1024]
#pragma unroll
        for (int mi = 0; mi < 2; ++mi)
#pragma unroll
            for (int q = 0; q < 2; ++q) {
                int gcol = bn + cb + q * 8;
                float bia0 = bias[gcol],       bia1 = bias[gcol + 1];
                float bib0 = bias[512 + gcol], bib1 = bias[512 + gcol + 1];
                const float* ca  = acc[mi][q];
                const float* cbv = acc[mi][2 + q];
                int ra = r0 + mi * 16;
                *(float2*)(outf + (size_t)ra * 1024 + gcol)
                    = make_float2(ca[0] + bia0, ca[1] + bia1);
                *(float2*)(outf + (size_t)ra * 1024 + 512 + gcol)
                    = make_float2(cbv[0] + bib0, cbv[1] + bib1);
                *(float2*)(outf + (size_t)(ra + 8) * 1024 + gcol)
                    = make_float2(ca[2] + bia0, ca[3] + bia1);
                *(float2*)(outf + (size_t)(ra + 8) * 1024 + 512 + gcol)
                    = make_float2(cbv[2] + bib0, cbv[3] + bib1);
            }
        return;
    }

    // mode 1: GLU -> smem g tile -> k3 partial MMA
    __syncthreads();
    {
#pragma unroll
        for (int mi = 0; mi < 2; ++mi)
#pragma unroll
            for (int q = 0; q < 2; ++q) {
                int gcol = bn + cb + q * 8;
                float bia0 = bias[gcol],       bia1 = bias[gcol + 1];
                float bib0 = bias[512 + gcol], bib1 = bias[512 + gcol + 1];
                const float* ca  = acc[mi][q];
                const float* cbv = acc[mi][2 + q];
                float g00 = (ca[0] + bia0) / (1.0f + __expf(-(cbv[0] + bib0)));
                float g01 = (ca[1] + bia1) / (1.0f + __expf(-(cbv[1] + bib1)));
                float g10 = (ca[2] + bia0) / (1.0f + __expf(-(cbv[2] + bib0)));
                float g11 = (ca[3] + bia1) / (1.0f + __expf(-(cbv[3] + bib1)));
                int lr = wm * 32 + (lane >> 2) + mi * 16;
                int lc = cb + q * 8;
                __nv_bfloat16 h0, l0, h1, l1;
                bf16split(g00, h0, l0); bf16split(g01, h1, l1);
                uint32_t o0 = (uint32_t)(lr * ROWE + lc) * 2;
                *(__nv_bfloat162*)(smem + o0)       = __nv_bfloat162(h0, h1);
                *(__nv_bfloat162*)(smem + GLO + o0) = __nv_bfloat162(l0, l1);
                bf16split(g10, h0, l0); bf16split(g11, h1, l1);
                uint32_t o1 = (uint32_t)((lr + 8) * ROWE + lc) * 2;
                *(__nv_bfloat162*)(smem + o1)       = __nv_bfloat162(h0, h1);
                *(__nv_bfloat162*)(smem + GLO + o1) = __nv_bfloat162(l0, l1);
            }
        __syncthreads();

        if (wid < 8) {
            float accs[4][4];
#pragma unroll
            for (int i = 0; i < 4; ++i)
#pragma unroll
                for (int j = 0; j < 4; ++j) accs[i][j] = 0.0f;

            const uint32_t a_b = sb + (uint32_t)((wid * 16 + (lane & 15)) * ROWE
                                                 + ((lane >> 4) << 3)) * 2;
            const uint32_t w_b = sb + W3_OFF
                + (uint32_t)(((lane >> 4) << 3) + (lane & 7)) * W3_ROWB
                + (uint32_t)((((lane >> 3) & 1) << 3)) * 2;
#pragma unroll
            for (int kk = 0; kk < 4; ++kk) {
                uint32_t ah[4], al[4];
                ldsm4(ah, a_b + kk * 32);
                ldsm4(al, a_b + GLO + kk * 32);
#pragma unroll
                for (int p = 0; p < 2; ++p) {
                    uint32_t bo = w_b + (uint32_t)(p * 16 * W3_ROWB) + kk * 32;
                    uint32_t bh4[4], bl4[4];
                    ldsm4(bh4, bo);
                    ldsm4(bl4, bo + W3_PREC);
#pragma unroll
                    for (int q = 0; q < 2; ++q) {
                        float* cc2 = accs[p * 2 + q];
                        mma16816(cc2, ah, &bh4[q * 2]);
                        mma16816(cc2, ah, &bl4[q * 2]);
                        mma16816(cc2, al, &bh4[q * 2]);
                    }
                }
            }
            float* kp = g_kpart + (size_t)blockIdx.x * NELEM;
#pragma unroll
            for (int nt = 0; nt < 4; ++nt)
#pragma unroll
                for (int half = 0; half < 2; ++half) {
                    int lr = wid * 16 + (lane >> 2) + half * 8;
                    int col = nt * 8 + (lane & 3) * 2;
                    *(float2*)(kp + (size_t)(bm + lr) * DDIM + col)
                        = make_float2(accs[nt][half * 2], accs[nt][half * 2 + 1]);
                }
        }
    }
}

// ---------------- layer1 theta-GEMM + inline RK4 update ----------------
// 512 threads, warps 4x4; CTA M=128, N=64 per half; K=32 (single pass).
// A tile (theta args) computed in-kernel from kpart/theta/ksum.
#define R2 40
#define A1P (128 * R2 * 2)               // 10240 per matrix per precision
#define SM1 (4 * A1P)                    // 40960

__global__ __launch_bounds__(512)
void glu1t(const float* __restrict__ W1, const float* __restrict__ b3,
           int it, float tval, float dt, int s_prev, int rd, int wr) {
    extern __shared__ char smem[];
    const uint32_t sb = smem_u32(smem);
    const int tid  = threadIdx.x;
    const int lane = tid & 31, wid = tid >> 5;
    const int wm = wid & 3, wn = wid >> 2;
    const int bm = blockIdx.y * 128, bn = blockIdx.x * 64;

    // B1t loads (128 out-rows x 32 k, hi+lo)
#pragma unroll
    for (int p = 0; p < 2; ++p) {
        int slot = p * 512 + tid;            // 0..1023
        int prec = slot >> 9;
        int s2 = slot & 511;
        int row = s2 >> 2, cc = s2 & 3;
        uint32_t so = (uint32_t)(2 * A1P + prec * A1P + (row * R2 + cc * 8) * 2);
        int brow = (row < 64) ? (bn + row) : (448 + bn + row);
        const __nv_bfloat16* g = (prec ? g_B1t_lo : g_B1t_hi) + (size_t)brow * 32 + cc * 8;
        cpasync16(sb + so, g);
    }
    CP_COMMIT();

    // A tile: compute RK4 args for rows bm..bm+127 x 32 cols
    {
        int r = tid >> 2, c0 = (tid & 3) * 8;
        size_t base = (size_t)(bm + r) * DDIM + c0;
        float th[8], kv[8], ks[8], arg[8];
        *(float4*)&th[0] = *(const float4*)&g_theta2[rd][base];
        *(float4*)&th[4] = *(const float4*)&g_theta2[rd][base + 4];

        if (it > 0) {
#pragma unroll
            for (int j = 0; j < 8; ++j) kv[j] = b3[c0 + j];
#pragma unroll
            for (int b = 0; b < 8; ++b) {
                float4 v0 = *(const float4*)&g_kpart[(size_t)b * NELEM + base];
                float4 v1 = *(const float4*)&g_kpart[(size_t)b * NELEM + base + 4];
                kv[0] += v0.x; kv[1] += v0.y; kv[2] += v0.z; kv[3] += v0.w;
                kv[4] += v1.x; kv[5] += v1.y; kv[6] += v1.z; kv[7] += v1.w;
            }
            if (s_prev >= 1) {
                *(float4*)&ks[0] = *(const float4*)&g_ksum2[rd][base];
                *(float4*)&ks[4] = *(const float4*)&g_ksum2[rd][base + 4];
            }
#pragma unroll
            for (int j = 0; j < 8; ++j) {
                if (s_prev == 0 || s_prev == 1) arg[j] = th[j] + 0.5f * dt * kv[j];
                else if (s_prev == 2)           arg[j] = th[j] + dt * kv[j];
                else                            arg[j] = th[j] + (dt / 6.0f) * (ks[j] + kv[j]);
            }
            if (blockIdx.x == 0) {
                float ksw[8], thw[8];
#pragma unroll
                for (int j = 0; j < 8; ++j) {
                    if (s_prev == 0)      { ksw[j] = kv[j];              thw[j] = th[j]; }
                    else if (s_prev <= 2) { ksw[j] = ks[j] + 2.0f*kv[j]; thw[j] = th[j]; }
                    else                  { ksw[j] = ks[j] + kv[j];      thw[j] = arg[j]; }
                }
                *(float4*)&g_ksum2[wr][base]      = *(float4*)&ksw[0];
                *(float4*)&g_ksum2[wr][base + 4]  = *(float4*)&ksw[4];
                *(float4*)&g_theta2[wr][base]     = *(float4*)&thw[0];
                *(float4*)&g_theta2[wr][base + 4] = *(float4*)&thw[4];
            }
        } else {
#pragma unroll
            for (int j = 0; j < 8; ++j) arg[j] = th[j];
        }
        uint32_t ao = (uint32_t)(r * R2 + c0) * 2;
#pragma unroll
        for (int j = 0; j < 4; ++j) {
            __nv_bfloat16 h0, l0, h1, l1;
            bf16split(arg[2 * j],     h0, l0);
            bf16split(arg[2 * j + 1], h1, l1);
            *(__nv_bfloat162*)(smem + ao + j * 4)       = __nv_bfloat162(h0, h1);
            *(__nv_bfloat162*)(smem + A1P + ao + j * 4) = __nv_bfloat162(l0, l1);
        }
    }
    CP_WAIT0();
    __syncthreads();

    // K=32 mainloop
    float acc[2][4][4];
#pragma unroll
    for (int i = 0; i < 2; ++i)
#pragma unroll
        for (int j = 0; j < 4; ++j)
#pragma unroll
            for (int q = 0; q < 4; ++q) acc[i][j][q] = 0.0f;

    const uint32_t a_off = (uint32_t)((wm * 32 + (lane & 15)) * R2
                                      + ((lane >> 4) << 3)) * 2;
    const uint32_t b_off = (uint32_t)((wn * 16 + ((lane >> 4) << 3) + (lane & 7)) * R2
                                      + (((lane >> 3) & 1) << 3)) * 2;
#pragma unroll
    for (int kk = 0; kk < 2; ++kk) {
        const uint32_t kb = (uint32_t)(kk * 16) * 2;
        uint32_t af[2][2][4];
#pragma unroll
        for (int mi = 0; mi < 2; ++mi) {
            uint32_t o = a_off + (uint32_t)(mi * 16 * R2) * 2 + kb;
            ldsm4(af[0][mi], sb + o);
            ldsm4(af[1][mi], sb + A1P + o);
        }
#pragma unroll
        for (int h = 0; h < 2; ++h) {
            uint32_t bh4[4], bl4[4];
            uint32_t o = b_off + (uint32_t)(h * 64 * R2) * 2 + kb;
            ldsm4(bh4, sb + 2 * A1P + o);
            ldsm4(bl4, sb + 3 * A1P + o);
#pragma unroll
            for (int mi = 0; mi < 2; ++mi)
#pragma unroll
                for (int q = 0; q < 2; ++q) {
                    float* cc2 = acc[mi][h * 2 + q];
                    mma16816(cc2, af[0][mi], &bh4[q * 2]);
                    mma16816(cc2, af[0][mi], &bl4[q * 2]);
                    mma16816(cc2, af[1][mi], &bh4[q * 2]);
                }
        }
    }

    // epilogue: + C0 + t*W1[32] , GLU, write h1 hi/lo
    const int r0 = bm + wm * 32 + (lane >> 2);
    const int cb = wn * 16 + (lane & 3) * 2;
    const float* w132 = W1 + (size_t)32 * 1024;
#pragma unroll
    for (int mi = 0; mi < 2; ++mi)
#pragma unroll
        for (int q = 0; q < 2; ++q) {
            int gcol = bn + cb + q * 8;
            int ra = r0 + mi * 16;
            float wa0 = tval * w132[gcol],       wa1 = tval * w132[gcol + 1];
            float wb0 = tval * w132[512 + gcol], wb1 = tval * w132[512 + gcol + 1];
            float2 c0a0 = *(const float2*)&g_C0[(size_t)ra * 1024 + gcol];
            float2 c0b0 = *(const float2*)&g_C0[(size_t)ra * 1024 + 512 + gcol];
            float2 c0a1 = *(const float2*)&g_C0[(size_t)(ra + 8) * 1024 + gcol];
            float2 c0b1 = *(const float2*)&g_C0[(size_t)(ra + 8) * 1024 + 512 + gcol];
            const float* ca  = acc[mi][q];
            const float* cbv = acc[mi][2 + q];
            float g00 = (ca[0] + c0a0.x + wa0) / (1.0f + __expf(-(cbv[0] + c0b0.x + wb0)));
            float g01 = (ca[1] + c0a0.y + wa1) / (1.0f + __expf(-(cbv[1] + c0b0.y + wb1)));
            float g10 = (ca[2] + c0a1.x + wa0) / (1.0f + __expf(-(cbv[2] + c0b1.x + wb0)));
            float g11 = (ca[3] + c0a1.y + wa1) / (1.0f + __expf(-(cbv[3] + c0b1.y + wb1)));
            size_t o0 = (size_t)ra * HID + gcol;
            size_t o1 = (size_t)(ra + 8) * HID + gcol;
            __nv_bfloat16 h0, l0, h1, l1;
            bf16split(g00, h0, l0); bf16split(g01, h1, l1);
            *(__nv_bfloat162*)(g_h1_hi + o0) = __nv_bfloat162(h0, h1);
            *(__nv_bfloat162*)(g_h1_lo + o0) = __nv_bfloat162(l0, l1);
            bf16split(g10, h0, l0); bf16split(g11, h1, l1);
            *(__nv_bfloat162*)(g_h1_hi + o1) = __nv_bfloat162(h0, h1);
            *(__nv_bfloat162*)(g_h1_lo + o1) = __nv_bfloat162(l0, l1);
        }
}

// ---------------- final RK4 combine ----------------
__global__ __launch_bounds__(256)
void final_update(const float* __restrict__ b3, float dt, float* __restrict__ out) {
    int idx = blockIdx.x * 256 + threadIdx.x;
    int c = idx & 31;
    float kv = b3[c];
#pragma unroll
    for (int b = 0; b < 8; ++b)
        kv += g_kpart[(size_t)b * NELEM + idx];
    out[idx] = g_theta2[1][idx] + (dt / 6.0f) * (g_ksum2[1][idx] + kv);
}

// ---------------- host launcher ----------------
extern "C" void kernel_launch(void* const* d_in, const int* in_sizes, int n_in,
                              void* d_out, int out_size) {
    const float* theta0  = (const float*)d_in[0];
    const float* context = (const float*)d_in[1];
    const float* W1      = (const float*)d_in[2];
    const float* b1      = (const float*)d_in[3];
    const float* W2      = (const float*)d_in[4];
    const float* b2      = (const float*)d_in[5];
    const float* W3      = (const float*)d_in[6];
    const float* b3      = (const float*)d_in[7];
    float* out = (float*)d_out;

    __nv_bfloat16 *h1h, *h1l, *b2h, *b2l, *ctxh, *ctxl, *b1ch, *b1cl;
    float* C0p;
    cudaGetSymbolAddress((void**)&h1h,  g_h1_hi);
    cudaGetSymbolAddress((void**)&h1l,  g_h1_lo);
    cudaGetSymbolAddress((void**)&b2h,  g_B2_hi);
    cudaGetSymbolAddress((void**)&b2l,  g_B2_lo);
    cudaGetSymbolAddress((void**)&ctxh, g_ctx_hi);
    cudaGetSymbolAddress((void**)&ctxl, g_ctx_lo);
    cudaGetSymbolAddress((void**)&b1ch, g_B1c_hi);
    cudaGetSymbolAddress((void**)&b1cl, g_B1c_lo);
    cudaGetSymbolAddress((void**)&C0p,  g_C0);

    cudaFuncSetAttribute(glu_mma, cudaFuncAttributeMaxDynamicSharedMemorySize, GLU_SMEM);
    cudaFuncSetAttribute(glu1t,   cudaFuncAttributeMaxDynamicSharedMemorySize, SM1);

    init_b1t<<<128, 256>>>(W1);
    init_b1c<<<512, 256>>>(W1);
    init_b2<<<2048, 256>>>(W2);
    init_w3t<<<64, 256>>>(W3);
    init_ctx<<<1024, 256>>>(context);
    init_theta<<<256, 256>>>(theta0);

    const float dt = 1.0f / NSTEPS;
    dim3 ggrid(8, 16);

    // C0 = ctx @ W1[33:161] + b1
    glu_mma<<<ggrid, 512, GLU_SMEM>>>(ctxh, ctxl, 128, 2, b1ch, b1cl, 128,
                                      b1, 0, C0p);

    for (int it = 0; it < NSTEPS * 4; ++it) {
        int s = it & 3;
        float tval = (float)(it >> 2) * dt + ((s == 0) ? 0.0f : (s < 3 ? 0.5f * dt : dt));
        int s_prev = (it - 1) & 3;
        int rd = (it == 0) ? 0 : ((it - 1) & 1);
        int wr = it & 1;
        glu1t<<<ggrid, 512, SM1>>>(W1, b3, it, tval, dt, s_prev, rd, wr);
        glu_mma<<<ggrid, 512, GLU_SMEM>>>(h1h, h1l, 512, 8, b2h, b2l, 512,
                                          b2, 1, nullptr);
    }
    final_update<<<256, 256>>>(b3, dt, out);
}